// round 1
// baseline (speedup 1.0000x reference)
#include <cuda_runtime.h>

#define NB 16
#define NN 1024
#define ND 1024
#define NU 512

// Scratch (device globals — no allocation allowed)
__device__ float g_vh[ND];
__device__ float g_vm[ND];
__device__ float g_c;                 // w_out.b_h + w_out.b_m + b_out
__device__ float g_sH[NB * NN];       // includes g_c folded in
__device__ float g_sM[NB * NN];

// ---------------------------------------------------------------------------
// Kernel 1: fold the U dimension.
// Blocks 0..3: v_h[d] = sum_u w_out[u]*W_h[u,d]; v_m likewise (coalesced over d).
// Block 4: scalar constant c = w_out.(b_h+b_m) + b_out.
// ---------------------------------------------------------------------------
__global__ void k_fold(const float* __restrict__ W_h, const float* __restrict__ b_h,
                       const float* __restrict__ W_m, const float* __restrict__ b_m,
                       const float* __restrict__ w_out, const float* __restrict__ b_out) {
    __shared__ float sw[NU];
    __shared__ float red[256];
    const int tid = threadIdx.x;
    for (int u = tid; u < NU; u += 256) sw[u] = w_out[u];
    __syncthreads();

    if (blockIdx.x < 4) {
        const int d = blockIdx.x * 256 + tid;
        float ah = 0.f, am = 0.f;
        #pragma unroll 8
        for (int u = 0; u < NU; ++u) {
            const float w = sw[u];
            ah = fmaf(w, W_h[(size_t)u * ND + d], ah);
            am = fmaf(w, W_m[(size_t)u * ND + d], am);
        }
        g_vh[d] = ah;
        g_vm[d] = am;
    } else {
        float acc = 0.f;
        for (int u = tid; u < NU; u += 256)
            acc = fmaf(sw[u], b_h[u] + b_m[u], acc);
        red[tid] = acc;
        __syncthreads();
        for (int s = 128; s > 0; s >>= 1) {
            if (tid < s) red[tid] += red[tid + s];
            __syncthreads();
        }
        if (tid == 0) g_c = red[0] + b_out[0];
    }
}

// ---------------------------------------------------------------------------
// Kernel 2: per-token dual dot products. One warp per token row (1024 floats),
// float4 loads, both dots in one pass over x (x read exactly once: 64 MiB).
// ---------------------------------------------------------------------------
__global__ void k_rowdots(const float* __restrict__ x) {
    __shared__ float4 svh[ND / 4];
    __shared__ float4 svm[ND / 4];
    const int tid = threadIdx.x;            // 256 threads = 8 warps
    svh[tid] = reinterpret_cast<const float4*>(g_vh)[tid];
    svm[tid] = reinterpret_cast<const float4*>(g_vm)[tid];
    __syncthreads();

    const int warp = tid >> 5, lane = tid & 31;
    const int row = blockIdx.x * 8 + warp;  // 0 .. NB*NN-1
    const float4* x4 = reinterpret_cast<const float4*>(x) + (size_t)row * (ND / 4);

    float ah = 0.f, am = 0.f;
    #pragma unroll
    for (int k = 0; k < 8; ++k) {
        const int idx = k * 32 + lane;
        const float4 xv = x4[idx];
        const float4 vh = svh[idx];
        const float4 vm = svm[idx];
        ah = fmaf(xv.x, vh.x, ah); ah = fmaf(xv.y, vh.y, ah);
        ah = fmaf(xv.z, vh.z, ah); ah = fmaf(xv.w, vh.w, ah);
        am = fmaf(xv.x, vm.x, am); am = fmaf(xv.y, vm.y, am);
        am = fmaf(xv.z, vm.z, am); am = fmaf(xv.w, vm.w, am);
    }
    #pragma unroll
    for (int off = 16; off; off >>= 1) {
        ah += __shfl_xor_sync(0xffffffffu, ah, off);
        am += __shfl_xor_sync(0xffffffffu, am, off);
    }
    if (lane == 0) {
        g_sH[row] = ah + g_c;   // fold all constants into sH
        g_sM[row] = am;
    }
}

// ---------------------------------------------------------------------------
// Kernel 3: outer broadcast-add. scores[b,i,j] = sH[b,i] + sM[b,j].
// Pure streaming write of 64 MiB via float4; sH/sM (128 KB) stay in L2.
// idx is the float4 index: 4*idx = b*N*N + i*N + j.
// ---------------------------------------------------------------------------
__global__ void k_outer(float* __restrict__ out) {
    const unsigned idx = blockIdx.x * 256u + threadIdx.x;  // < 4,194,304
    const unsigned j4 = idx & 255u;        // j/4, N/4 = 256
    const unsigned bi = idx >> 8;          // b*N + i
    const unsigned b  = bi >> 10;          // /N

    const float s = g_sH[bi];
    const float4 m = reinterpret_cast<const float4*>(g_sM)[(b << 8) + j4];
    reinterpret_cast<float4*>(out)[idx] =
        make_float4(s + m.x, s + m.y, s + m.z, s + m.w);
}

extern "C" void kernel_launch(void* const* d_in, const int* in_sizes, int n_in,
                              void* d_out, int out_size) {
    const float* x     = (const float*)d_in[0];
    const float* W_h   = (const float*)d_in[1];
    const float* b_h   = (const float*)d_in[2];
    const float* W_m   = (const float*)d_in[3];
    const float* b_m   = (const float*)d_in[4];
    const float* w_out = (const float*)d_in[5];
    const float* b_out = (const float*)d_in[6];
    float* out = (float*)d_out;

    k_fold<<<5, 256>>>(W_h, b_h, W_m, b_m, w_out, b_out);
    k_rowdots<<<(NB * NN) / 8, 256>>>(x);
    k_outer<<<(NB * NN * NN) / (4 * 256), 256>>>(out);
}

// round 2
// speedup vs baseline: 2.9339x; 2.9339x over previous
#include <cuda_runtime.h>

#define NB 16
#define NN 1024
#define ND 1024
#define NU 512

// Scratch (device globals — no allocation allowed)
__device__ float g_vh[ND];
__device__ float g_vm[ND];
__device__ float g_c;                 // w_out.(b_h+b_m) + b_out
__device__ float g_sH[NB * NN];       // constant c folded in
__device__ float g_sM[NB * NN];

// ---------------------------------------------------------------------------
// Kernel 0: zero the fold accumulators + compute scalar constant c.
// ---------------------------------------------------------------------------
__global__ void k_init(const float* __restrict__ b_h, const float* __restrict__ b_m,
                       const float* __restrict__ w_out, const float* __restrict__ b_out) {
    __shared__ float red[256];
    const int tid = threadIdx.x;
    #pragma unroll
    for (int k = 0; k < ND / 256; ++k) {
        g_vh[k * 256 + tid] = 0.f;
        g_vm[k * 256 + tid] = 0.f;
    }
    float acc = 0.f;
    for (int u = tid; u < NU; u += 256)
        acc = fmaf(w_out[u], b_h[u] + b_m[u], acc);
    red[tid] = acc;
    __syncthreads();
    for (int s = 128; s > 0; s >>= 1) {
        if (tid < s) red[tid] += red[tid + s];
        __syncthreads();
    }
    if (tid == 0) g_c = red[0] + b_out[0];
}

// ---------------------------------------------------------------------------
// Kernel 1: fold the U dimension with real parallelism.
// Grid (4 d-blocks, 32 u-chunks). Each block reads a coalesced [16u x 256d]
// tile of both W matrices and atomically accumulates partial dot products.
// ---------------------------------------------------------------------------
__global__ void k_fold(const float* __restrict__ W_h, const float* __restrict__ W_m,
                       const float* __restrict__ w_out) {
    const int d  = blockIdx.x * 256 + threadIdx.x;
    const int u0 = blockIdx.y * 16;

    float ah = 0.f, am = 0.f;
    #pragma unroll
    for (int k = 0; k < 16; ++k) {
        const int u = u0 + k;
        const float w = __ldg(&w_out[u]);
        ah = fmaf(w, __ldg(&W_h[(size_t)u * ND + d]), ah);
        am = fmaf(w, __ldg(&W_m[(size_t)u * ND + d]), am);
    }
    atomicAdd(&g_vh[d], ah);
    atomicAdd(&g_vm[d], am);
}

// ---------------------------------------------------------------------------
// Kernel 2: per-token dual dot products. One warp per token row (1024 floats),
// float4 loads, both dots in one pass over x (x read exactly once: 64 MiB).
// ---------------------------------------------------------------------------
__global__ void k_rowdots(const float* __restrict__ x) {
    __shared__ float4 svh[ND / 4];
    __shared__ float4 svm[ND / 4];
    const int tid = threadIdx.x;            // 256 threads = 8 warps
    svh[tid] = reinterpret_cast<const float4*>(g_vh)[tid];
    svm[tid] = reinterpret_cast<const float4*>(g_vm)[tid];
    __syncthreads();

    const int warp = tid >> 5, lane = tid & 31;
    const int row = blockIdx.x * 8 + warp;  // 0 .. NB*NN-1
    const float4* x4 = reinterpret_cast<const float4*>(x) + (size_t)row * (ND / 4);

    float ah = 0.f, am = 0.f;
    #pragma unroll
    for (int k = 0; k < 8; ++k) {
        const int idx = k * 32 + lane;
        const float4 xv = x4[idx];
        const float4 vh = svh[idx];
        const float4 vm = svm[idx];
        ah = fmaf(xv.x, vh.x, ah); ah = fmaf(xv.y, vh.y, ah);
        ah = fmaf(xv.z, vh.z, ah); ah = fmaf(xv.w, vh.w, ah);
        am = fmaf(xv.x, vm.x, am); am = fmaf(xv.y, vm.y, am);
        am = fmaf(xv.z, vm.z, am); am = fmaf(xv.w, vm.w, am);
    }
    #pragma unroll
    for (int off = 16; off; off >>= 1) {
        ah += __shfl_xor_sync(0xffffffffu, ah, off);
        am += __shfl_xor_sync(0xffffffffu, am, off);
    }
    if (lane == 0) {
        g_sH[row] = ah + g_c;   // fold all constants into sH
        g_sM[row] = am;
    }
}

// ---------------------------------------------------------------------------
// Kernel 3: outer broadcast-add. scores[b,i,j] = sH[b,i] + sM[b,j].
// Pure streaming write of 64 MiB via float4; sH/sM (128 KB) stay in L2.
// idx is the float4 index: 4*idx = b*N*N + i*N + j.
// ---------------------------------------------------------------------------
__global__ void k_outer(float* __restrict__ out) {
    const unsigned idx = blockIdx.x * 256u + threadIdx.x;  // < 4,194,304
    const unsigned j4 = idx & 255u;        // j/4, N/4 = 256
    const unsigned bi = idx >> 8;          // b*N + i
    const unsigned b  = bi >> 10;          // /N

    const float s = g_sH[bi];
    const float4 m = reinterpret_cast<const float4*>(g_sM)[(b << 8) + j4];
    reinterpret_cast<float4*>(out)[idx] =
        make_float4(s + m.x, s + m.y, s + m.z, s + m.w);
}

extern "C" void kernel_launch(void* const* d_in, const int* in_sizes, int n_in,
                              void* d_out, int out_size) {
    const float* x     = (const float*)d_in[0];
    const float* W_h   = (const float*)d_in[1];
    const float* b_h   = (const float*)d_in[2];
    const float* W_m   = (const float*)d_in[3];
    const float* b_m   = (const float*)d_in[4];
    const float* w_out = (const float*)d_in[5];
    const float* b_out = (const float*)d_in[6];
    float* out = (float*)d_out;

    k_init<<<1, 256>>>(b_h, b_m, w_out, b_out);
    k_fold<<<dim3(4, 32), 256>>>(W_h, W_m, w_out);
    k_rowdots<<<(NB * NN) / 8, 256>>>(x);
    k_outer<<<(NB * NN * NN) / (4 * 256), 256>>>(out);
}